// round 14
// baseline (speedup 1.0000x reference)
#include <cuda_runtime.h>
#include <cuda_fp16.h>
#include <math.h>

#define BB 32
#define SQ 200
#define SMEMLEN 1024
#define DMODEL 1024
#define NH 16
#define HD 64
#define DFF 4096
#define NT (BB*SQ)        // 6400 target tokens
#define MTOK (BB*SMEMLEN) // 32768 memory tokens
#define EPS 1e-5f

// ---------------- scratch ----------------
__device__ float  g_x[NT*DMODEL];
__device__ __half g_qkh[NT*2048];       // SA q|k packed (row stride 2048)
__device__ __half g_vh[NT*DMODEL];      // SA v
__device__ __half g_qh[NT*DMODEL];      // CA q
__device__ __half g_kvh[MTOK*2048];     // CA k|v packed (row stride 2048)
__device__ __half g_hh[NT*DMODEL];
__device__ __half g_ropedh[NT*DMODEL];
__device__ __half g_attnh[NT*DMODEL];
__device__ __half g_ffhh[NT*DFF];
__device__ __half g_memh[MTOK*DMODEL];
__device__ __half g_wh[16*1024*1024];   // fp16 weights (packed)

#define OW_SA_IN   0
#define OW_SA_OUT  3145728
#define OW_CA_IN   4194304
#define OW_CA_OUT  7340032
#define OW_FF1     8388608
#define OW_FF2     12582912

// ---------------- fp32 -> fp16 convert (MLP=4 grid-stride) ----------------
__global__ void to_half_kernel(const float4* __restrict__ in,
                               uint2* __restrict__ out, int n4) {
    int idx = blockIdx.x * blockDim.x + threadIdx.x;
    int T = gridDim.x * blockDim.x;
    for (int base = idx; base < n4; base += 4 * T) {
        float4 v[4];
        int k1 = base + T, k2 = base + 2 * T, k3 = base + 3 * T;
        v[0] = in[base];
        if (k1 < n4) v[1] = in[k1];
        if (k2 < n4) v[2] = in[k2];
        if (k3 < n4) v[3] = in[k3];
        {
            __half2 h0 = __floats2half2_rn(v[0].x, v[0].y);
            __half2 h1 = __floats2half2_rn(v[0].z, v[0].w);
            uint2 o; o.x = *(unsigned*)&h0; o.y = *(unsigned*)&h1;
            out[base] = o;
        }
        if (k1 < n4) {
            __half2 h0 = __floats2half2_rn(v[1].x, v[1].y);
            __half2 h1 = __floats2half2_rn(v[1].z, v[1].w);
            uint2 o; o.x = *(unsigned*)&h0; o.y = *(unsigned*)&h1;
            out[k1] = o;
        }
        if (k2 < n4) {
            __half2 h0 = __floats2half2_rn(v[2].x, v[2].y);
            __half2 h1 = __floats2half2_rn(v[2].z, v[2].w);
            uint2 o; o.x = *(unsigned*)&h0; o.y = *(unsigned*)&h1;
            out[k2] = o;
        }
        if (k3 < n4) {
            __half2 h0 = __floats2half2_rn(v[3].x, v[3].y);
            __half2 h1 = __floats2half2_rn(v[3].z, v[3].w);
            uint2 o; o.x = *(unsigned*)&h0; o.y = *(unsigned*)&h1;
            out[k3] = o;
        }
    }
}

// ---------------- LayerNorm (fp32 in, fp16 out; optional fused RoPE out) -------
__global__ __launch_bounds__(256) void ln_kernel(const float* __restrict__ x,
                                                 const float* __restrict__ g,
                                                 const float* __restrict__ b,
                                                 __half* __restrict__ out,
                                                 __half* __restrict__ out_roped) {
    __shared__ float rs[8], rss[8];
    int t = blockIdx.x;
    int tid = threadIdx.x;
    const float4* xr = (const float4*)(x + (size_t)t * DMODEL);
    float4 v = xr[tid];
    float s  = v.x + v.y + v.z + v.w;
    float ss = v.x*v.x + v.y*v.y + v.z*v.z + v.w*v.w;
    #pragma unroll
    for (int o = 16; o; o >>= 1) {
        s  += __shfl_xor_sync(0xffffffffu, s, o);
        ss += __shfl_xor_sync(0xffffffffu, ss, o);
    }
    int lane = tid & 31, wid = tid >> 5;
    if (lane == 0) { rs[wid] = s; rss[wid] = ss; }
    __syncthreads();
    float ts = 0.f, tss = 0.f;
    #pragma unroll
    for (int w = 0; w < 8; w++) { ts += rs[w]; tss += rss[w]; }
    float mu  = ts * (1.0f / DMODEL);
    float var = tss * (1.0f / DMODEL) - mu * mu;
    float r   = rsqrtf(var + EPS);
    float4 gv = ((const float4*)g)[tid];
    float4 bv = ((const float4*)b)[tid];
    float ox = (v.x - mu) * r * gv.x + bv.x;
    float oy = (v.y - mu) * r * gv.y + bv.y;
    float oz = (v.z - mu) * r * gv.z + bv.z;
    float ow = (v.w - mu) * r * gv.w + bv.w;
    {
        __half2 h0 = __floats2half2_rn(ox, oy);
        __half2 h1 = __floats2half2_rn(oz, ow);
        uint2 o;
        o.x = *(unsigned*)&h0;
        o.y = *(unsigned*)&h1;
        ((uint2*)(out + (size_t)t * DMODEL))[tid] = o;
    }
    if (out_roped) {
        int e0 = tid * 4;
        int i0 = (e0 & 63) >> 1;
        int spos = t % SQ;
        float f0 = __expf(-9.210340371976184f * (2.0f * i0) * (1.0f / 64.0f));
        float f1 = __expf(-9.210340371976184f * (2.0f * (i0 + 1)) * (1.0f / 64.0f));
        float sn0, cs0, sn1, cs1;
        sincosf((float)spos * f0, &sn0, &cs0);
        sincosf((float)spos * f1, &sn1, &cs1);
        float r0x = ox * cs0 - oy * sn0;
        float r0y = oy * cs0 + ox * sn0;
        float r1x = oz * cs1 - ow * sn1;
        float r1y = ow * cs1 + oz * sn1;
        __half2 h0 = __floats2half2_rn(r0x, r0y);
        __half2 h1 = __floats2half2_rn(r1x, r1y);
        uint2 o;
        o.x = *(unsigned*)&h0;
        o.y = *(unsigned*)&h1;
        ((uint2*)(out_roped + (size_t)t * DMODEL))[tid] = o;
    }
}

// ---------------- common mma helpers ----------------
__device__ __forceinline__ void cpa16(unsigned dst, const void* src) {
    asm volatile("cp.async.cg.shared.global [%0], [%1], 16;\n" :: "r"(dst), "l"(src));
}
__device__ __forceinline__ void ldsm4(unsigned& r0, unsigned& r1, unsigned& r2, unsigned& r3,
                                      unsigned a) {
    asm volatile("ldmatrix.sync.aligned.m8n8.x4.shared.b16 {%0,%1,%2,%3}, [%4];"
                 : "=r"(r0), "=r"(r1), "=r"(r2), "=r"(r3) : "r"(a));
}
__device__ __forceinline__ void ldsm4t(unsigned& r0, unsigned& r1, unsigned& r2, unsigned& r3,
                                       unsigned a) {
    asm volatile("ldmatrix.sync.aligned.m8n8.x4.trans.shared.b16 {%0,%1,%2,%3}, [%4];"
                 : "=r"(r0), "=r"(r1), "=r"(r2), "=r"(r3) : "r"(a));
}
__device__ __forceinline__ void mma16816(float* c, unsigned a0, unsigned a1, unsigned a2,
                                         unsigned a3, unsigned b0, unsigned b1) {
    asm volatile(
        "mma.sync.aligned.m16n8k16.row.col.f32.f16.f16.f32 "
        "{%0,%1,%2,%3}, {%4,%5,%6,%7}, {%8,%9}, {%0,%1,%2,%3};"
        : "+f"(c[0]), "+f"(c[1]), "+f"(c[2]), "+f"(c[3])
        : "r"(a0), "r"(a1), "r"(a2), "r"(a3), "r"(b0), "r"(b1));
}

// ---------------- fp16 tensor-core GEMM (256x128 tile, warp 64x64) ------------
// C[M,N] = A[M,K] @ W[N,K]^T + bias  (flag1 relu, flag2 fp32 res, flag4 fp16 out)
// 3-stage cp.async, M % 256 == 0, N % 128 == 0, K % 64 == 0.
#define BKH 64
#define RSH 72
#define NSTG 3
#define STG_A_H (256 * RSH)              // halves
#define STG_W_H (128 * RSH)
#define STG_B  ((STG_A_H + STG_W_H) * 2) // 55296 bytes per stage
#define GSMEM  (NSTG * STG_B)            // 165888 bytes

__global__ __launch_bounds__(256, 1) void hgemm(const __half* __restrict__ A,
                                                const __half* __restrict__ W,
                                                const float* __restrict__ bias,
                                                const float* __restrict__ res,
                                                void* __restrict__ Cout,
                                                int M, int N, int K, int flags) {
    extern __shared__ __half smh[];
    int tid = threadIdx.x;
    int wid = tid >> 5, lane = tid & 31;
    int gid = lane >> 2, tig = lane & 3;
    int row0 = blockIdx.y * 256;
    int col0 = blockIdx.x * 128;
    int wm = (wid & 3) * 64;            // warp m offset (0..192)
    int wn = (wid >> 2) * 64;           // warp n offset (0 or 64)

    unsigned sbase = (unsigned)__cvta_generic_to_shared(smh);
    unsigned stgA[NSTG], stgW[NSTG];
    #pragma unroll
    for (int s = 0; s < NSTG; s++) {
        stgA[s] = sbase + s * STG_B;
        stgW[s] = stgA[s] + STG_A_H * 2;
    }

    // A loader: thread t -> row t, 8 chunks of 16B. W loader: row t>>1, 4 chunks.
    const __half* Ab = A + (size_t)(row0 + tid) * K;
    int wlr = tid >> 1;
    int wlc = (tid & 1) * 32;           // halves
    const __half* Wb = W + (size_t)(col0 + wlr) * K + wlc;

    float c[4][8][4];
    #pragma unroll
    for (int mi = 0; mi < 4; mi++)
        #pragma unroll
        for (int ni = 0; ni < 8; ni++)
            #pragma unroll
            for (int q = 0; q < 4; q++) c[mi][ni][q] = 0.f;

    int nk = K / BKH;

    auto stage_load = [&](int kt) {
        int st = kt % NSTG;
        int k0 = kt * BKH;
        #pragma unroll
        for (int i = 0; i < 8; i++)
            cpa16(stgA[st] + (tid * RSH + i * 8) * 2, Ab + k0 + i * 8);
        #pragma unroll
        for (int i = 0; i < 4; i++)
            cpa16(stgW[st] + (wlr * RSH + wlc + i * 8) * 2, Wb + k0 + i * 8);
        asm volatile("cp.async.commit_group;\n");
    };

    stage_load(0);
    stage_load(1);

    int a_row = lane & 15;
    int a_col = (lane >> 4) * 8;
    int b_row = (lane & 7) + ((lane & 16) >> 1);
    int b_col = lane & 8;

    unsigned af[2][4][4], bf[2][4][4];

    for (int kt = 0; kt < nk; kt++) {
        if (kt < nk - 1) asm volatile("cp.async.wait_group 1;\n");
        else             asm volatile("cp.async.wait_group 0;\n");
        __syncthreads();

        if (kt + 2 < nk) stage_load(kt + 2);

        int st = kt % NSTG;
        unsigned sAu = stgA[st];
        unsigned sWu = stgW[st];

        auto load_frags = [&](int buf, int ks) {
            int kb = ks * 16;
            #pragma unroll
            for (int mi = 0; mi < 4; mi++)
                ldsm4(af[buf][mi][0], af[buf][mi][1], af[buf][mi][2], af[buf][mi][3],
                      sAu + ((wm + mi * 16 + a_row) * RSH + kb + a_col) * 2);
            #pragma unroll
            for (int p = 0; p < 4; p++)
                ldsm4(bf[buf][p][0], bf[buf][p][1], bf[buf][p][2], bf[buf][p][3],
                      sWu + ((wn + p * 16 + b_row) * RSH + kb + b_col) * 2);
        };

        load_frags(0, 0);
        #pragma unroll
        for (int ks = 0; ks < 4; ks++) {
            int cur = ks & 1;
            if (ks < 3) load_frags(cur ^ 1, ks + 1);
            #pragma unroll
            for (int mi = 0; mi < 4; mi++)
                #pragma unroll
                for (int p = 0; p < 4; p++) {
                    mma16816(c[mi][2*p],   af[cur][mi][0], af[cur][mi][1], af[cur][mi][2],
                             af[cur][mi][3], bf[cur][p][0], bf[cur][p][1]);
                    mma16816(c[mi][2*p+1], af[cur][mi][0], af[cur][mi][1], af[cur][mi][2],
                             af[cur][mi][3], bf[cur][p][2], bf[cur][p][3]);
                }
        }
    }

    bool use_relu = (flags & 1) != 0;
    bool use_res  = (flags & 2) != 0;
    bool out_h    = (flags & 4) != 0;
    float* Cf = (float*)Cout;
    __half* Ch = (__half*)Cout;
    #pragma unroll
    for (int mi = 0; mi < 4; mi++) {
        #pragma unroll
        for (int ni = 0; ni < 8; ni++) {
            int colg = col0 + wn + ni * 8 + tig * 2;
            int r0 = row0 + wm + mi * 16 + gid;
            int r1 = r0 + 8;
            float b0 = bias[colg], b1 = bias[colg + 1];
            float2 o0, o1;
            o0.x = c[mi][ni][0] + b0; o0.y = c[mi][ni][1] + b1;
            o1.x = c[mi][ni][2] + b0; o1.y = c[mi][ni][3] + b1;
            size_t i0 = (size_t)r0 * N + colg;
            size_t i1 = (size_t)r1 * N + colg;
            if (use_res) {
                float2 rv0 = *(const float2*)(res + i0);
                float2 rv1 = *(const float2*)(res + i1);
                o0.x += rv0.x; o0.y += rv0.y;
                o1.x += rv1.x; o1.y += rv1.y;
            }
            if (use_relu) {
                o0.x = fmaxf(o0.x, 0.f); o0.y = fmaxf(o0.y, 0.f);
                o1.x = fmaxf(o1.x, 0.f); o1.y = fmaxf(o1.y, 0.f);
            }
            if (out_h) {
                __half2 h0 = __floats2half2_rn(o0.x, o0.y);
                __half2 h1 = __floats2half2_rn(o1.x, o1.y);
                *(unsigned*)(Ch + i0) = *(unsigned*)&h0;
                *(unsigned*)(Ch + i1) = *(unsigned*)&h1;
            } else {
                *(float2*)(Cf + i0) = o0;
                *(float2*)(Cf + i1) = o1;
            }
        }
    }
}

// ---------------- fp16 tensor-core flash attention (AQ=128, 8 warps) ----------
#define AQ 128
#define AK 64
#define AH 72   // halves per smem row

__global__ __launch_bounds__(256) void attn_h(const __half* __restrict__ Q,
                                              const __half* __restrict__ Km,
                                              const __half* __restrict__ Vm,
                                              __half* __restrict__ O,
                                              int Sq, int Sk, int causal,
                                              int qstr, int kstr, int vstr) {
    __shared__ __half Qs[AQ*AH], Ks[AK*AH], Vs[AK*AH];

    int qt = blockIdx.x, h = blockIdx.y, b = blockIdx.z;
    int tid = threadIdx.x;
    int wid = tid >> 5, lane = tid & 31;

    unsigned sQ = (unsigned)__cvta_generic_to_shared(Qs);
    unsigned sK = (unsigned)__cvta_generic_to_shared(Ks);
    unsigned sV = (unsigned)__cvta_generic_to_shared(Vs);

    {
        int r = tid >> 1;
        int cb = (tid & 1) * 32;
        int qgl = qt * AQ + r;
        const __half* src = Q + ((size_t)(b * Sq + qgl)) * qstr + h * HD + cb;
        uint4 z = {0u, 0u, 0u, 0u};
        #pragma unroll
        for (int i = 0; i < 4; i++) {
            uint4 v = (qgl < Sq) ? *(const uint4*)(src + i * 8) : z;
            *(uint4*)&Qs[r * AH + cb + i * 8] = v;
        }
    }
    __syncthreads();

    int a_row = lane & 15;
    int a_col = (lane >> 4) * 8;
    unsigned aq[4][4];
    #pragma unroll
    for (int ks = 0; ks < 4; ks++)
        ldsm4(aq[ks][0], aq[ks][1], aq[ks][2], aq[ks][3],
              sQ + ((wid * 16 + a_row) * AH + ks * 16 + a_col) * 2);

    int b_row = (lane & 7) + ((lane & 16) >> 1);
    int b_col = lane & 8;

    int r0 = lane >> 2, tig = lane & 3;
    int qgl0 = qt * AQ + wid * 16 + r0;
    int qgl1 = qgl0 + 8;
    float m0 = -1e30f, m1 = -1e30f, l0 = 0.f, l1 = 0.f;
    float o[8][4];
    #pragma unroll
    for (int j = 0; j < 8; j++)
        #pragma unroll
        for (int q = 0; q < 4; q++) o[j][q] = 0.f;

    int q_hi = qt * AQ + AQ - 1;
    int keff = causal ? min(q_hi + 1, Sk) : Sk;
    int ntiles = (keff + AK - 1) / AK;

    int kr = tid >> 3;
    int kc = (tid & 7) * 8;
    uint4 pk[2], pv[2];
    {
        uint4 z = {0u, 0u, 0u, 0u};
        #pragma unroll
        for (int j2 = 0; j2 < 2; j2++) {
            int kg = kr + 32 * j2;
            bool ok = kg < Sk;
            pk[j2] = ok ? *(const uint4*)(Km + ((size_t)(b * Sk + kg)) * kstr + h * HD + kc) : z;
            pv[j2] = ok ? *(const uint4*)(Vm + ((size_t)(b * Sk + kg)) * vstr + h * HD + kc) : z;
        }
    }

    for (int kt = 0; kt < ntiles; kt++) {
        #pragma unroll
        for (int j2 = 0; j2 < 2; j2++) {
            *(uint4*)&Ks[(kr + 32 * j2) * AH + kc] = pk[j2];
            *(uint4*)&Vs[(kr + 32 * j2) * AH + kc] = pv[j2];
        }
        __syncthreads();

        if (kt + 1 < ntiles) {
            uint4 z = {0u, 0u, 0u, 0u};
            #pragma unroll
            for (int j2 = 0; j2 < 2; j2++) {
                int kg = (kt + 1) * AK + kr + 32 * j2;
                bool ok = kg < Sk;
                pk[j2] = ok ? *(const uint4*)(Km + ((size_t)(b * Sk + kg)) * kstr + h * HD + kc) : z;
                pv[j2] = ok ? *(const uint4*)(Vm + ((size_t)(b * Sk + kg)) * vstr + h * HD + kc) : z;
            }
        }

        float s[8][4];
        #pragma unroll
        for (int j = 0; j < 8; j++)
            #pragma unroll
            for (int q = 0; q < 4; q++) s[j][q] = 0.f;

        #pragma unroll
        for (int ks = 0; ks < 4; ks++) {
            #pragma unroll
            for (int p = 0; p < 4; p++) {
                unsigned bf0, bf1, bf2, bf3;
                ldsm4(bf0, bf1, bf2, bf3,
                      sK + ((p * 16 + b_row) * AH + ks * 16 + b_col) * 2);
                mma16816(s[2*p],   aq[ks][0], aq[ks][1], aq[ks][2], aq[ks][3], bf0, bf1);
                mma16816(s[2*p+1], aq[ks][0], aq[ks][1], aq[ks][2], aq[ks][3], bf2, bf3);
            }
        }

        int kvalid0 = causal ? min(qgl0 + 1, Sk) : Sk;
        int kvalid1 = causal ? min(qgl1 + 1, Sk) : Sk;
        int kgb = kt * AK + tig * 2;
        float tm0 = -1e30f, tm1 = -1e30f;
        #pragma unroll
        for (int j = 0; j < 8; j++) {
            int kg = kgb + j * 8;
            s[j][0] = (kg     < kvalid0) ? s[j][0] * 0.125f : -1e30f;
            s[j][1] = (kg + 1 < kvalid0) ? s[j][1] * 0.125f : -1e30f;
            s[j][2] = (kg     < kvalid1) ? s[j][2] * 0.125f : -1e30f;
            s[j][3] = (kg + 1 < kvalid1) ? s[j][3] * 0.125f : -1e30f;
            tm0 = fmaxf(tm0, fmaxf(s[j][0], s[j][1]));
            tm1 = fmaxf(tm1, fmaxf(s[j][2], s[j][3]));
        }
        tm0 = fmaxf(tm0, __shfl_xor_sync(0xffffffffu, tm0, 1));
        tm0 = fmaxf(tm0, __shfl_xor_sync(0xffffffffu, tm0, 2));
        tm1 = fmaxf(tm1, __shfl_xor_sync(0xffffffffu, tm1, 1));
        tm1 = fmaxf(tm1, __shfl_xor_sync(0xffffffffu, tm1, 2));

        float mn0 = fmaxf(m0, tm0), mn1 = fmaxf(m1, tm1);
        float sc0 = __expf(m0 - mn0), sc1 = __expf(m1 - mn1);
        float ps0 = 0.f, ps1 = 0.f;
        #pragma unroll
        for (int j = 0; j < 8; j++) {
            s[j][0] = __expf(s[j][0] - mn0);
            s[j][1] = __expf(s[j][1] - mn0);
            s[j][2] = __expf(s[j][2] - mn1);
            s[j][3] = __expf(s[j][3] - mn1);
            ps0 += s[j][0] + s[j][1];
            ps1 += s[j][2] + s[j][3];
        }
        ps0 += __shfl_xor_sync(0xffffffffu, ps0, 1);
        ps0 += __shfl_xor_sync(0xffffffffu, ps0, 2);
        ps1 += __shfl_xor_sync(0xffffffffu, ps1, 1);
        ps1 += __shfl_xor_sync(0xffffffffu, ps1, 2);
        l0 = l0 * sc0 + ps0;  m0 = mn0;
        l1 = l1 * sc1 + ps1;  m1 = mn1;
        #pragma unroll
        for (int j = 0; j < 8; j++) {
            o[j][0] *= sc0; o[j][1] *= sc0;
            o[j][2] *= sc1; o[j][3] *= sc1;
        }

        unsigned pa[4][4];
        #pragma unroll
        for (int t = 0; t < 4; t++) {
            __half2 h0 = __floats2half2_rn(s[2*t][0],   s[2*t][1]);
            __half2 h1 = __floats2half2_rn(s[2*t][2],   s[2*t][3]);
            __half2 h2 = __floats2half2_rn(s[2*t+1][0], s[2*t+1][1]);
            __half2 h3 = __floats2half2_rn(s[2*t+1][2], s[2*t+1][3]);
            pa[t][0] = *(unsigned*)&h0;
            pa[t][1] = *(unsigned*)&h1;
            pa[t][2] = *(unsigned*)&h2;
            pa[t][3] = *(unsigned*)&h3;
        }

        #pragma unroll
        for (int t = 0; t < 4; t++) {
            #pragma unroll
            for (int p = 0; p < 4; p++) {
                unsigned bv0, bv1, bv2, bv3;
                ldsm4t(bv0, bv1, bv2, bv3,
                       sV + ((t * 16 + (lane & 15)) * AH + p * 16 + (lane >> 4) * 8) * 2);
                mma16816(o[2*p],   pa[t][0], pa[t][1], pa[t][2], pa[t][3], bv0, bv1);
                mma16816(o[2*p+1], pa[t][0], pa[t][1], pa[t][2], pa[t][3], bv2, bv3);
            }
        }
        __syncthreads();
    }

    float inv0 = 1.0f / l0, inv1 = 1.0f / l1;
    #pragma unroll
    for (int j = 0; j < 8; j++) {
        int d = j * 8 + tig * 2;
        if (qgl0 < Sq) {
            __half2 h0 = __floats2half2_rn(o[j][0] * inv0, o[j][1] * inv0);
            *(unsigned*)(O + ((size_t)(b * Sq + qgl0)) * DMODEL + h * HD + d) = *(unsigned*)&h0;
        }
        if (qgl1 < Sq) {
            __half2 h1 = __floats2half2_rn(o[j][2] * inv1, o[j][3] * inv1);
            *(unsigned*)(O + ((size_t)(b * Sq + qgl1)) * DMODEL + h * HD + d) = *(unsigned*)&h1;
        }
    }
}

// ---------------- host orchestration ----------------
extern "C" void kernel_launch(void* const* d_in, const int* in_sizes, int n_in,
                              void* d_out, int out_size) {
    const float* tgt      = (const float*)d_in[0];
    const float* memory   = (const float*)d_in[1];
    const float* sa_in_w  = (const float*)d_in[2];
    const float* sa_in_b  = (const float*)d_in[3];
    const float* sa_out_w = (const float*)d_in[4];
    const float* sa_out_b = (const float*)d_in[5];
    const float* ca_in_w  = (const float*)d_in[6];
    const float* ca_in_b  = (const float*)d_in[7];
    const float* ca_out_w = (const float*)d_in[8];
    const float* ca_out_b = (const float*)d_in[9];
    const float* ff1_w    = (const float*)d_in[10];
    const float* ff1_b    = (const float*)d_in[11];
    const float* ff2_w    = (const float*)d_in[12];
    const float* ff2_b    = (const float*)d_in[13];
    const float* ln1_g    = (const float*)d_in[14];
    const float* ln1_b    = (const float*)d_in[15];
    const float* ln2_g    = (const float*)d_in[16];
    const float* ln2_b    = (const float*)d_in[17];
    const float* ln3_g    = (const float*)d_in[18];
    const float* ln3_b    = (const float*)d_in[19];
    float* out = (float*)d_out;

    float *p_x;
    __half *p_qkh, *p_vh, *p_qh, *p_kvh, *p_hh, *p_ropedh, *p_attnh, *p_ffhh, *p_memh, *p_wh;
    cudaGetSymbolAddress((void**)&p_x,      g_x);
    cudaGetSymbolAddress((void**)&p_qkh,    g_qkh);
    cudaGetSymbolAddress((void**)&p_vh,     g_vh);
    cudaGetSymbolAddress((void**)&p_qh,     g_qh);
    cudaGetSymbolAddress((void**)&p_kvh,    g_kvh);
    cudaGetSymbolAddress((void**)&p_hh,     g_hh);
    cudaGetSymbolAddress((void**)&p_ropedh, g_ropedh);
    cudaGetSymbolAddress((void**)&p_attnh,  g_attnh);
    cudaGetSymbolAddress((void**)&p_ffhh,   g_ffhh);
    cudaGetSymbolAddress((void**)&p_memh,   g_memh);
    cudaGetSymbolAddress((void**)&p_wh,     g_wh);

    static int init_done = 0;
    static cudaStream_t s2;
    static cudaEvent_t evFork, evJoin;
    if (!init_done) {
        cudaFuncSetAttribute(hgemm, cudaFuncAttributeMaxDynamicSharedMemorySize, GSMEM);
        cudaStreamCreateWithFlags(&s2, cudaStreamNonBlocking);
        cudaEventCreateWithFlags(&evFork, cudaEventDisableTiming);
        cudaEventCreateWithFlags(&evJoin, cudaEventDisableTiming);
        init_done = 1;
    }

    auto tohalf = [](const float* src, __half* dst, int n, cudaStream_t st) {
        int n4 = n / 4;
        int blocks = (n4 + 1023) / 1024;
        to_half_kernel<<<blocks, 256, 0, st>>>((const float4*)src, (uint2*)dst, n4);
    };

    tohalf(sa_in_w,  p_wh + OW_SA_IN,  3 * DMODEL * DMODEL, 0);
    tohalf(sa_out_w, p_wh + OW_SA_OUT, DMODEL * DMODEL, 0);
    tohalf(ca_in_w,  p_wh + OW_CA_IN,  3 * DMODEL * DMODEL, 0);
    tohalf(ca_out_w, p_wh + OW_CA_OUT, DMODEL * DMODEL, 0);
    tohalf(ff1_w,    p_wh + OW_FF1,    DFF * DMODEL, 0);
    tohalf(ff2_w,    p_wh + OW_FF2,    DMODEL * DFF, 0);

    dim3 gemm_nt_d(DMODEL / 128, NT / 256);         // (8, 25)
    dim3 gemm_nt_2d(2048 / 128, NT / 256);          // (16, 25)
    dim3 gemm_mt_2d(2048 / 128, MTOK / 256);        // (16, 128)
    dim3 gemm_ff1(DFF / 128, NT / 256);             // (32, 25)
    int qtiles = (SQ + AQ - 1) / AQ;                // 2

    // ---- fork: stream2 does memory convert + big CA k|v GEMM concurrently ----
    cudaEventRecord(evFork, 0);
    cudaStreamWaitEvent(s2, evFork, 0);
    tohalf(memory, p_memh, MTOK * DMODEL, s2);
    hgemm<<<gemm_mt_2d, 256, GSMEM, s2>>>(p_memh, p_wh + OW_CA_IN + (size_t)DMODEL*DMODEL,
                                          ca_in_b + DMODEL, nullptr, p_kvh, MTOK, 2048, DMODEL, 4);
    cudaEventRecord(evJoin, s2);

    // ---- main stream: self-attention block ----
    ln_kernel<<<NT, 256>>>(tgt, ln1_g, ln1_b, p_hh, p_ropedh);   // fused LN+RoPE
    hgemm<<<gemm_nt_2d, 256, GSMEM>>>(p_ropedh, p_wh + OW_SA_IN, sa_in_b, nullptr, p_qkh, NT, 2048, DMODEL, 4);
    hgemm<<<gemm_nt_d, 256, GSMEM>>>(p_hh, p_wh + OW_SA_IN + (size_t)2*DMODEL*DMODEL, sa_in_b + 2*DMODEL, nullptr, p_vh, NT, DMODEL, DMODEL, 4);
    attn_h<<<dim3(qtiles, NH, BB), 256>>>(p_qkh, p_qkh + 1024, p_vh, p_attnh, SQ, SQ, 1, 2048, 2048, 1024);
    hgemm<<<gemm_nt_d, 256, GSMEM>>>(p_attnh, p_wh + OW_SA_OUT, sa_out_b, tgt, p_x, NT, DMODEL, DMODEL, 2);

    // ---- cross-attention block ----
    ln_kernel<<<NT, 256>>>(p_x, ln2_g, ln2_b, p_hh, nullptr);
    hgemm<<<gemm_nt_d, 256, GSMEM>>>(p_hh, p_wh + OW_CA_IN, ca_in_b, nullptr, p_qh, NT, DMODEL, DMODEL, 4);
    cudaStreamWaitEvent(0, evJoin, 0);   // join: kv GEMM must be done
    attn_h<<<dim3(qtiles, NH, BB), 256>>>(p_qh, p_kvh, p_kvh + 1024, p_attnh, SQ, SMEMLEN, 0, 1024, 2048, 2048);
    hgemm<<<gemm_nt_d, 256, GSMEM>>>(p_attnh, p_wh + OW_CA_OUT, ca_out_b, p_x, p_x, NT, DMODEL, DMODEL, 2);

    // ---- feed-forward block ----
    ln_kernel<<<NT, 256>>>(p_x, ln3_g, ln3_b, p_hh, nullptr);
    hgemm<<<gemm_ff1, 256, GSMEM>>>(p_hh,   p_wh + OW_FF1, ff1_b, nullptr, p_ffhh, NT, DFF, DMODEL, 1 | 4);
    hgemm<<<gemm_nt_d, 256, GSMEM>>>(p_ffhh, p_wh + OW_FF2, ff2_b, p_x, out, NT, DMODEL, DFF, 2);
}

// round 15
// speedup vs baseline: 1.2319x; 1.2319x over previous
#include <cuda_runtime.h>
#include <cuda_fp16.h>
#include <math.h>

#define BB 32
#define SQ 200
#define SMEMLEN 1024
#define DMODEL 1024
#define NH 16
#define HD 64
#define DFF 4096
#define NT (BB*SQ)        // 6400 target tokens
#define MTOK (BB*SMEMLEN) // 32768 memory tokens
#define EPS 1e-5f

// ---------------- scratch ----------------
__device__ float  g_x[NT*DMODEL];
__device__ __half g_qkh[NT*2048];       // SA q|k packed (row stride 2048)
__device__ __half g_vh[NT*DMODEL];      // SA v
__device__ __half g_qh[NT*DMODEL];      // CA q
__device__ __half g_kvh[MTOK*2048];     // CA k|v packed (row stride 2048)
__device__ __half g_hh[NT*DMODEL];
__device__ __half g_ropedh[NT*DMODEL];
__device__ __half g_attnh[NT*DMODEL];
__device__ __half g_ffhh[NT*DFF];
__device__ __half g_memh[MTOK*DMODEL];
__device__ __half g_wh[16*1024*1024];   // fp16 weights (packed)

#define OW_SA_IN   0
#define OW_SA_OUT  3145728
#define OW_CA_IN   4194304
#define OW_CA_OUT  7340032
#define OW_FF1     8388608
#define OW_FF2     12582912

// ---------------- single fp32->fp16 convert (memory, on stream2) ----------------
__global__ void to_half_kernel(const float4* __restrict__ in,
                               uint2* __restrict__ out, int n4) {
    int idx = blockIdx.x * blockDim.x + threadIdx.x;
    int T = gridDim.x * blockDim.x;
    for (int base = idx; base < n4; base += 4 * T) {
        #pragma unroll
        for (int u = 0; u < 4; u++) {
            int k = base + u * T;
            if (k < n4) {
                float4 v = in[k];
                __half2 h0 = __floats2half2_rn(v.x, v.y);
                __half2 h1 = __floats2half2_rn(v.z, v.w);
                uint2 o; o.x = *(unsigned*)&h0; o.y = *(unsigned*)&h1;
                out[k] = o;
            }
        }
    }
}

// ---------------- merged 6-segment weight convert (one launch) ----------------
// segment sizes in float4: 786432, 262144, 786432, 262144, 1048576, 1048576
#define SEG0 786432
#define SEG1 (SEG0 + 262144)     // 1048576
#define SEG2 (SEG1 + 786432)     // 1835008
#define SEG3 (SEG2 + 262144)     // 2097152
#define SEG4 (SEG3 + 1048576)    // 3145728
#define SEGT (SEG4 + 1048576)    // 4194304
__global__ void to_half_multi(const float4* __restrict__ s0, const float4* __restrict__ s1,
                              const float4* __restrict__ s2, const float4* __restrict__ s3,
                              const float4* __restrict__ s4, const float4* __restrict__ s5,
                              uint2* __restrict__ dst /* g_wh as uint2 */) {
    int idx = blockIdx.x * blockDim.x + threadIdx.x;
    int T = gridDim.x * blockDim.x;
    for (int base = idx; base < SEGT; base += 4 * T) {
        #pragma unroll
        for (int u = 0; u < 4; u++) {
            int k = base + u * T;
            if (k < SEGT) {
                float4 v;
                if      (k < SEG0) v = s0[k];
                else if (k < SEG1) v = s1[k - SEG0];
                else if (k < SEG2) v = s2[k - SEG1];
                else if (k < SEG3) v = s3[k - SEG2];
                else if (k < SEG4) v = s4[k - SEG3];
                else               v = s5[k - SEG4];
                __half2 h0 = __floats2half2_rn(v.x, v.y);
                __half2 h1 = __floats2half2_rn(v.z, v.w);
                uint2 o; o.x = *(unsigned*)&h0; o.y = *(unsigned*)&h1;
                dst[k] = o;
            }
        }
    }
}

// ---------------- LayerNorm (fp32 in, fp16 out; optional fused RoPE out) -------
__global__ __launch_bounds__(256) void ln_kernel(const float* __restrict__ x,
                                                 const float* __restrict__ g,
                                                 const float* __restrict__ b,
                                                 __half* __restrict__ out,
                                                 __half* __restrict__ out_roped) {
    __shared__ float rs[8], rss[8];
    int t = blockIdx.x;
    int tid = threadIdx.x;
    const float4* xr = (const float4*)(x + (size_t)t * DMODEL);
    float4 v = xr[tid];
    float s  = v.x + v.y + v.z + v.w;
    float ss = v.x*v.x + v.y*v.y + v.z*v.z + v.w*v.w;
    #pragma unroll
    for (int o = 16; o; o >>= 1) {
        s  += __shfl_xor_sync(0xffffffffu, s, o);
        ss += __shfl_xor_sync(0xffffffffu, ss, o);
    }
    int lane = tid & 31, wid = tid >> 5;
    if (lane == 0) { rs[wid] = s; rss[wid] = ss; }
    __syncthreads();
    float ts = 0.f, tss = 0.f;
    #pragma unroll
    for (int w = 0; w < 8; w++) { ts += rs[w]; tss += rss[w]; }
    float mu  = ts * (1.0f / DMODEL);
    float var = tss * (1.0f / DMODEL) - mu * mu;
    float r   = rsqrtf(var + EPS);
    float4 gv = ((const float4*)g)[tid];
    float4 bv = ((const float4*)b)[tid];
    float ox = (v.x - mu) * r * gv.x + bv.x;
    float oy = (v.y - mu) * r * gv.y + bv.y;
    float oz = (v.z - mu) * r * gv.z + bv.z;
    float ow = (v.w - mu) * r * gv.w + bv.w;
    {
        __half2 h0 = __floats2half2_rn(ox, oy);
        __half2 h1 = __floats2half2_rn(oz, ow);
        uint2 o;
        o.x = *(unsigned*)&h0;
        o.y = *(unsigned*)&h1;
        ((uint2*)(out + (size_t)t * DMODEL))[tid] = o;
    }
    if (out_roped) {
        int e0 = tid * 4;
        int i0 = (e0 & 63) >> 1;
        int spos = t % SQ;
        float f0 = __expf(-9.210340371976184f * (2.0f * i0) * (1.0f / 64.0f));
        float f1 = __expf(-9.210340371976184f * (2.0f * (i0 + 1)) * (1.0f / 64.0f));
        float sn0, cs0, sn1, cs1;
        sincosf((float)spos * f0, &sn0, &cs0);
        sincosf((float)spos * f1, &sn1, &cs1);
        float r0x = ox * cs0 - oy * sn0;
        float r0y = oy * cs0 + ox * sn0;
        float r1x = oz * cs1 - ow * sn1;
        float r1y = ow * cs1 + oz * sn1;
        __half2 h0 = __floats2half2_rn(r0x, r0y);
        __half2 h1 = __floats2half2_rn(r1x, r1y);
        uint2 o;
        o.x = *(unsigned*)&h0;
        o.y = *(unsigned*)&h1;
        ((uint2*)(out_roped + (size_t)t * DMODEL))[tid] = o;
    }
}

// ---------------- common mma helpers ----------------
__device__ __forceinline__ void cpa16(unsigned dst, const void* src) {
    asm volatile("cp.async.cg.shared.global [%0], [%1], 16;\n" :: "r"(dst), "l"(src));
}
__device__ __forceinline__ void ldsm4(unsigned& r0, unsigned& r1, unsigned& r2, unsigned& r3,
                                      unsigned a) {
    asm volatile("ldmatrix.sync.aligned.m8n8.x4.shared.b16 {%0,%1,%2,%3}, [%4];"
                 : "=r"(r0), "=r"(r1), "=r"(r2), "=r"(r3) : "r"(a));
}
__device__ __forceinline__ void ldsm4t(unsigned& r0, unsigned& r1, unsigned& r2, unsigned& r3,
                                       unsigned a) {
    asm volatile("ldmatrix.sync.aligned.m8n8.x4.trans.shared.b16 {%0,%1,%2,%3}, [%4];"
                 : "=r"(r0), "=r"(r1), "=r"(r2), "=r"(r3) : "r"(a));
}
__device__ __forceinline__ void mma16816(float* c, unsigned a0, unsigned a1, unsigned a2,
                                         unsigned a3, unsigned b0, unsigned b1) {
    asm volatile(
        "mma.sync.aligned.m16n8k16.row.col.f32.f16.f16.f32 "
        "{%0,%1,%2,%3}, {%4,%5,%6,%7}, {%8,%9}, {%0,%1,%2,%3};"
        : "+f"(c[0]), "+f"(c[1]), "+f"(c[2]), "+f"(c[3])
        : "r"(a0), "r"(a1), "r"(a2), "r"(a3), "r"(b0), "r"(b1));
}

// ---------------- fp16 tensor-core GEMM (128x128, 3-stage cp.async, R13) ------
#define BKH 64
#define RSH 72
#define NSTG 3
#define STGH (2 * 128 * RSH)
#define GSMEM (NSTG * STGH * 2)          // 110592 bytes

__global__ __launch_bounds__(256, 2) void hgemm(const __half* __restrict__ A,
                                                const __half* __restrict__ W,
                                                const float* __restrict__ bias,
                                                const float* __restrict__ res,
                                                void* __restrict__ Cout,
                                                int M, int N, int K, int flags) {
    extern __shared__ __half smh[];
    int tid = threadIdx.x;
    int wid = tid >> 5, lane = tid & 31;
    int gid = lane >> 2, tig = lane & 3;
    int row0 = blockIdx.y * 128;
    int col0 = blockIdx.x * 128;
    int wm = (wid & 3) * 32;
    int wn = (wid >> 2) * 64;

    unsigned sbase = (unsigned)__cvta_generic_to_shared(smh);
    unsigned stgA[NSTG], stgW[NSTG];
    #pragma unroll
    for (int s = 0; s < NSTG; s++) {
        stgA[s] = sbase + s * STGH * 2;
        stgW[s] = stgA[s] + 128 * RSH * 2;
    }

    int lr = tid >> 1;
    int lc = (tid & 1) * 32;
    const __half* Ab = A + (size_t)(row0 + lr) * K + lc;
    const __half* Wb = W + (size_t)(col0 + lr) * K + lc;

    float c[2][8][4];
    #pragma unroll
    for (int mi = 0; mi < 2; mi++)
        #pragma unroll
        for (int ni = 0; ni < 8; ni++)
            #pragma unroll
            for (int q = 0; q < 4; q++) c[mi][ni][q] = 0.f;

    int nk = K / BKH;

    #pragma unroll
    for (int ps = 0; ps < 2; ps++) {
        int k0 = ps * BKH;
        #pragma unroll
        for (int cch = 0; cch < 4; cch++) {
            unsigned soff = (lr * RSH + lc + cch * 8) * 2;
            cpa16(stgA[ps] + soff, Ab + k0 + cch * 8);
            cpa16(stgW[ps] + soff, Wb + k0 + cch * 8);
        }
        asm volatile("cp.async.commit_group;\n");
    }

    int a_row = lane & 15;
    int a_col = (lane >> 4) * 8;
    int b_row = (lane & 7) + ((lane & 16) >> 1);
    int b_col = lane & 8;

    unsigned af[2][2][4], bf[2][4][4];

    for (int kt = 0; kt < nk; kt++) {
        if (kt < nk - 1) asm volatile("cp.async.wait_group 1;\n");
        else             asm volatile("cp.async.wait_group 0;\n");
        __syncthreads();

        if (kt + 2 < nk) {
            int st = (kt + 2) % NSTG;
            int k0 = (kt + 2) * BKH;
            #pragma unroll
            for (int cch = 0; cch < 4; cch++) {
                unsigned soff = (lr * RSH + lc + cch * 8) * 2;
                cpa16(stgA[st] + soff, Ab + k0 + cch * 8);
                cpa16(stgW[st] + soff, Wb + k0 + cch * 8);
            }
            asm volatile("cp.async.commit_group;\n");
        }

        int st = kt % NSTG;
        unsigned sAu = stgA[st];
        unsigned sWu = stgW[st];

        auto load_frags = [&](int buf, int ks) {
            int kb = ks * 16;
            #pragma unroll
            for (int mi = 0; mi < 2; mi++)
                ldsm4(af[buf][mi][0], af[buf][mi][1], af[buf][mi][2], af[buf][mi][3],
                      sAu + ((wm + mi * 16 + a_row) * RSH + kb + a_col) * 2);
            #pragma unroll
            for (int p = 0; p < 4; p++)
                ldsm4(bf[buf][p][0], bf[buf][p][1], bf[buf][p][2], bf[buf][p][3],
                      sWu + ((wn + p * 16 + b_row) * RSH + kb + b_col) * 2);
        };

        load_frags(0, 0);
        #pragma unroll
        for (int ks = 0; ks < 4; ks++) {
            int cur = ks & 1;
            if (ks < 3) load_frags(cur ^ 1, ks + 1);
            #pragma unroll
            for (int mi = 0; mi < 2; mi++)
                #pragma unroll
                for (int p = 0; p < 4; p++) {
                    mma16816(c[mi][2*p],   af[cur][mi][0], af[cur][mi][1], af[cur][mi][2],
                             af[cur][mi][3], bf[cur][p][0], bf[cur][p][1]);
                    mma16816(c[mi][2*p+1], af[cur][mi][0], af[cur][mi][1], af[cur][mi][2],
                             af[cur][mi][3], bf[cur][p][2], bf[cur][p][3]);
                }
        }
    }

    bool use_relu = (flags & 1) != 0;
    bool use_res  = (flags & 2) != 0;
    bool out_h    = (flags & 4) != 0;
    float* Cf = (float*)Cout;
    __half* Ch = (__half*)Cout;
    #pragma unroll
    for (int mi = 0; mi < 2; mi++) {
        #pragma unroll
        for (int ni = 0; ni < 8; ni++) {
            int colg = col0 + wn + ni * 8 + tig * 2;
            int r0 = row0 + wm + mi * 16 + gid;
            int r1 = r0 + 8;
            float b0 = bias[colg], b1 = bias[colg + 1];
            float2 o0, o1;
            o0.x = c[mi][ni][0] + b0; o0.y = c[mi][ni][1] + b1;
            o1.x = c[mi][ni][2] + b0; o1.y = c[mi][ni][3] + b1;
            size_t i0 = (size_t)r0 * N + colg;
            size_t i1 = (size_t)r1 * N + colg;
            if (use_res) {
                float2 rv0 = *(const float2*)(res + i0);
                float2 rv1 = *(const float2*)(res + i1);
                o0.x += rv0.x; o0.y += rv0.y;
                o1.x += rv1.x; o1.y += rv1.y;
            }
            if (use_relu) {
                o0.x = fmaxf(o0.x, 0.f); o0.y = fmaxf(o0.y, 0.f);
                o1.x = fmaxf(o1.x, 0.f); o1.y = fmaxf(o1.y, 0.f);
            }
            if (out_h) {
                __half2 h0 = __floats2half2_rn(o0.x, o0.y);
                __half2 h1 = __floats2half2_rn(o1.x, o1.y);
                *(unsigned*)(Ch + i0) = *(unsigned*)&h0;
                *(unsigned*)(Ch + i1) = *(unsigned*)&h1;
            } else {
                *(float2*)(Cf + i0) = o0;
                *(float2*)(Cf + i1) = o1;
            }
        }
    }
}

// ---------------- fp16 tensor-core flash attention (AQ=128, 8 warps) ----------
#define AQ 128
#define AK 64
#define AH 72   // halves per smem row

__global__ __launch_bounds__(256) void attn_h(const __half* __restrict__ Q,
                                              const __half* __restrict__ Km,
                                              const __half* __restrict__ Vm,
                                              __half* __restrict__ O,
                                              int Sq, int Sk, int causal,
                                              int qstr, int kstr, int vstr) {
    __shared__ __half Qs[AQ*AH], Ks[AK*AH], Vs[AK*AH];

    int qt = blockIdx.x, h = blockIdx.y, b = blockIdx.z;
    int tid = threadIdx.x;
    int wid = tid >> 5, lane = tid & 31;

    unsigned sQ = (unsigned)__cvta_generic_to_shared(Qs);
    unsigned sK = (unsigned)__cvta_generic_to_shared(Ks);
    unsigned sV = (unsigned)__cvta_generic_to_shared(Vs);

    {
        int r = tid >> 1;
        int cb = (tid & 1) * 32;
        int qgl = qt * AQ + r;
        const __half* src = Q + ((size_t)(b * Sq + qgl)) * qstr + h * HD + cb;
        uint4 z = {0u, 0u, 0u, 0u};
        #pragma unroll
        for (int i = 0; i < 4; i++) {
            uint4 v = (qgl < Sq) ? *(const uint4*)(src + i * 8) : z;
            *(uint4*)&Qs[r * AH + cb + i * 8] = v;
        }
    }
    __syncthreads();

    int a_row = lane & 15;
    int a_col = (lane >> 4) * 8;
    unsigned aq[4][4];
    #pragma unroll
    for (int ks = 0; ks < 4; ks++)
        ldsm4(aq[ks][0], aq[ks][1], aq[ks][2], aq[ks][3],
              sQ + ((wid * 16 + a_row) * AH + ks * 16 + a_col) * 2);

    int b_row = (lane & 7) + ((lane & 16) >> 1);
    int b_col = lane & 8;

    int r0 = lane >> 2, tig = lane & 3;
    int qgl0 = qt * AQ + wid * 16 + r0;
    int qgl1 = qgl0 + 8;
    float m0 = -1e30f, m1 = -1e30f, l0 = 0.f, l1 = 0.f;
    float o[8][4];
    #pragma unroll
    for (int j = 0; j < 8; j++)
        #pragma unroll
        for (int q = 0; q < 4; q++) o[j][q] = 0.f;

    int q_hi = qt * AQ + AQ - 1;
    int keff = causal ? min(q_hi + 1, Sk) : Sk;
    int ntiles = (keff + AK - 1) / AK;

    int kr = tid >> 3;
    int kc = (tid & 7) * 8;
    uint4 pk[2], pv[2];
    {
        uint4 z = {0u, 0u, 0u, 0u};
        #pragma unroll
        for (int j2 = 0; j2 < 2; j2++) {
            int kg = kr + 32 * j2;
            bool ok = kg < Sk;
            pk[j2] = ok ? *(const uint4*)(Km + ((size_t)(b * Sk + kg)) * kstr + h * HD + kc) : z;
            pv[j2] = ok ? *(const uint4*)(Vm + ((size_t)(b * Sk + kg)) * vstr + h * HD + kc) : z;
        }
    }

    for (int kt = 0; kt < ntiles; kt++) {
        #pragma unroll
        for (int j2 = 0; j2 < 2; j2++) {
            *(uint4*)&Ks[(kr + 32 * j2) * AH + kc] = pk[j2];
            *(uint4*)&Vs[(kr + 32 * j2) * AH + kc] = pv[j2];
        }
        __syncthreads();

        if (kt + 1 < ntiles) {
            uint4 z = {0u, 0u, 0u, 0u};
            #pragma unroll
            for (int j2 = 0; j2 < 2; j2++) {
                int kg = (kt + 1) * AK + kr + 32 * j2;
                bool ok = kg < Sk;
                pk[j2] = ok ? *(const uint4*)(Km + ((size_t)(b * Sk + kg)) * kstr + h * HD + kc) : z;
                pv[j2] = ok ? *(const uint4*)(Vm + ((size_t)(b * Sk + kg)) * vstr + h * HD + kc) : z;
            }
        }

        float s[8][4];
        #pragma unroll
        for (int j = 0; j < 8; j++)
            #pragma unroll
            for (int q = 0; q < 4; q++) s[j][q] = 0.f;

        #pragma unroll
        for (int ks = 0; ks < 4; ks++) {
            #pragma unroll
            for (int p = 0; p < 4; p++) {
                unsigned bf0, bf1, bf2, bf3;
                ldsm4(bf0, bf1, bf2, bf3,
                      sK + ((p * 16 + b_row) * AH + ks * 16 + b_col) * 2);
                mma16816(s[2*p],   aq[ks][0], aq[ks][1], aq[ks][2], aq[ks][3], bf0, bf1);
                mma16816(s[2*p+1], aq[ks][0], aq[ks][1], aq[ks][2], aq[ks][3], bf2, bf3);
            }
        }

        int kvalid0 = causal ? min(qgl0 + 1, Sk) : Sk;
        int kvalid1 = causal ? min(qgl1 + 1, Sk) : Sk;
        int kgb = kt * AK + tig * 2;
        float tm0 = -1e30f, tm1 = -1e30f;
        #pragma unroll
        for (int j = 0; j < 8; j++) {
            int kg = kgb + j * 8;
            s[j][0] = (kg     < kvalid0) ? s[j][0] * 0.125f : -1e30f;
            s[j][1] = (kg + 1 < kvalid0) ? s[j][1] * 0.125f : -1e30f;
            s[j][2] = (kg     < kvalid1) ? s[j][2] * 0.125f : -1e30f;
            s[j][3] = (kg + 1 < kvalid1) ? s[j][3] * 0.125f : -1e30f;
            tm0 = fmaxf(tm0, fmaxf(s[j][0], s[j][1]));
            tm1 = fmaxf(tm1, fmaxf(s[j][2], s[j][3]));
        }
        tm0 = fmaxf(tm0, __shfl_xor_sync(0xffffffffu, tm0, 1));
        tm0 = fmaxf(tm0, __shfl_xor_sync(0xffffffffu, tm0, 2));
        tm1 = fmaxf(tm1, __shfl_xor_sync(0xffffffffu, tm1, 1));
        tm1 = fmaxf(tm1, __shfl_xor_sync(0xffffffffu, tm1, 2));

        float mn0 = fmaxf(m0, tm0), mn1 = fmaxf(m1, tm1);
        float sc0 = __expf(m0 - mn0), sc1 = __expf(m1 - mn1);
        float ps0 = 0.f, ps1 = 0.f;
        #pragma unroll
        for (int j = 0; j < 8; j++) {
            s[j][0] = __expf(s[j][0] - mn0);
            s[j][1] = __expf(s[j][1] - mn0);
            s[j][2] = __expf(s[j][2] - mn1);
            s[j][3] = __expf(s[j][3] - mn1);
            ps0 += s[j][0] + s[j][1];
            ps1 += s[j][2] + s[j][3];
        }
        ps0 += __shfl_xor_sync(0xffffffffu, ps0, 1);
        ps0 += __shfl_xor_sync(0xffffffffu, ps0, 2);
        ps1 += __shfl_xor_sync(0xffffffffu, ps1, 1);
        ps1 += __shfl_xor_sync(0xffffffffu, ps1, 2);
        l0 = l0 * sc0 + ps0;  m0 = mn0;
        l1 = l1 * sc1 + ps1;  m1 = mn1;
        #pragma unroll
        for (int j = 0; j < 8; j++) {
            o[j][0] *= sc0; o[j][1] *= sc0;
            o[j][2] *= sc1; o[j][3] *= sc1;
        }

        unsigned pa[4][4];
        #pragma unroll
        for (int t = 0; t < 4; t++) {
            __half2 h0 = __floats2half2_rn(s[2*t][0],   s[2*t][1]);
            __half2 h1 = __floats2half2_rn(s[2*t][2],   s[2*t][3]);
            __half2 h2 = __floats2half2_rn(s[2*t+1][0], s[2*t+1][1]);
            __half2 h3 = __floats2half2_rn(s[2*t+1][2], s[2*t+1][3]);
            pa[t][0] = *(unsigned*)&h0;
            pa[t][1] = *(unsigned*)&h1;
            pa[t][2] = *(unsigned*)&h2;
            pa[t][3] = *(unsigned*)&h3;
        }

        #pragma unroll
        for (int t = 0; t < 4; t++) {
            #pragma unroll
            for (int p = 0; p < 4; p++) {
                unsigned bv0, bv1, bv2, bv3;
                ldsm4t(bv0, bv1, bv2, bv3,
                       sV + ((t * 16 + (lane & 15)) * AH + p * 16 + (lane >> 4) * 8) * 2);
                mma16816(o[2*p],   pa[t][0], pa[t][1], pa[t][2], pa[t][3], bv0, bv1);
                mma16816(o[2*p+1], pa[t][0], pa[t][1], pa[t][2], pa[t][3], bv2, bv3);
            }
        }
        __syncthreads();
    }

    float inv0 = 1.0f / l0, inv1 = 1.0f / l1;
    #pragma unroll
    for (int j = 0; j < 8; j++) {
        int d = j * 8 + tig * 2;
        if (qgl0 < Sq) {
            __half2 h0 = __floats2half2_rn(o[j][0] * inv0, o[j][1] * inv0);
            *(unsigned*)(O + ((size_t)(b * Sq + qgl0)) * DMODEL + h * HD + d) = *(unsigned*)&h0;
        }
        if (qgl1 < Sq) {
            __half2 h1 = __floats2half2_rn(o[j][2] * inv1, o[j][3] * inv1);
            *(unsigned*)(O + ((size_t)(b * Sq + qgl1)) * DMODEL + h * HD + d) = *(unsigned*)&h1;
        }
    }
}

// ---------------- host orchestration ----------------
extern "C" void kernel_launch(void* const* d_in, const int* in_sizes, int n_in,
                              void* d_out, int out_size) {
    const float* tgt      = (const float*)d_in[0];
    const float* memory   = (const float*)d_in[1];
    const float* sa_in_w  = (const float*)d_in[2];
    const float* sa_in_b  = (const float*)d_in[3];
    const float* sa_out_w = (const float*)d_in[4];
    const float* sa_out_b = (const float*)d_in[5];
    const float* ca_in_w  = (const float*)d_in[6];
    const float* ca_in_b  = (const float*)d_in[7];
    const float* ca_out_w = (const float*)d_in[8];
    const float* ca_out_b = (const float*)d_in[9];
    const float* ff1_w    = (const float*)d_in[10];
    const float* ff1_b    = (const float*)d_in[11];
    const float* ff2_w    = (const float*)d_in[12];
    const float* ff2_b    = (const float*)d_in[13];
    const float* ln1_g    = (const float*)d_in[14];
    const float* ln1_b    = (const float*)d_in[15];
    const float* ln2_g    = (const float*)d_in[16];
    const float* ln2_b    = (const float*)d_in[17];
    const float* ln3_g    = (const float*)d_in[18];
    const float* ln3_b    = (const float*)d_in[19];
    float* out = (float*)d_out;

    float *p_x;
    __half *p_qkh, *p_vh, *p_qh, *p_kvh, *p_hh, *p_ropedh, *p_attnh, *p_ffhh, *p_memh, *p_wh;
    cudaGetSymbolAddress((void**)&p_x,      g_x);
    cudaGetSymbolAddress((void**)&p_qkh,    g_qkh);
    cudaGetSymbolAddress((void**)&p_vh,     g_vh);
    cudaGetSymbolAddress((void**)&p_qh,     g_qh);
    cudaGetSymbolAddress((void**)&p_kvh,    g_kvh);
    cudaGetSymbolAddress((void**)&p_hh,     g_hh);
    cudaGetSymbolAddress((void**)&p_ropedh, g_ropedh);
    cudaGetSymbolAddress((void**)&p_attnh,  g_attnh);
    cudaGetSymbolAddress((void**)&p_ffhh,   g_ffhh);
    cudaGetSymbolAddress((void**)&p_memh,   g_memh);
    cudaGetSymbolAddress((void**)&p_wh,     g_wh);

    static int init_done = 0;
    static cudaStream_t s2;
    static cudaEvent_t evFork, evJoin;
    if (!init_done) {
        cudaFuncSetAttribute(hgemm, cudaFuncAttributeMaxDynamicSharedMemorySize, GSMEM);
        cudaStreamCreateWithFlags(&s2, cudaStreamNonBlocking);
        cudaEventCreateWithFlags(&evFork, cudaEventDisableTiming);
        cudaEventCreateWithFlags(&evJoin, cudaEventDisableTiming);
        init_done = 1;
    }

    dim3 gemm_nt_d(DMODEL / 128, NT / 128);
    dim3 gemm_nt_2d(2048 / 128, NT / 128);
    dim3 gemm_mt_2d(2048 / 128, MTOK / 128);
    dim3 gemm_ff1(DFF / 128, NT / 128);
    int qtiles = (SQ + AQ - 1) / AQ;                // 2

    // ---- all six weight converts in ONE launch ----
    to_half_multi<<<1024, 256>>>((const float4*)sa_in_w, (const float4*)sa_out_w,
                                 (const float4*)ca_in_w, (const float4*)ca_out_w,
                                 (const float4*)ff1_w,   (const float4*)ff2_w,
                                 (uint2*)p_wh);

    // ---- fork: stream2 does memory convert + big CA k|v GEMM concurrently ----
    cudaEventRecord(evFork, 0);
    cudaStreamWaitEvent(s2, evFork, 0);
    {
        int n4 = (MTOK * DMODEL) / 4;
        to_half_kernel<<<(n4 + 1023) / 1024, 256, 0, s2>>>((const float4*)memory, (uint2*)p_memh, n4);
    }
    hgemm<<<gemm_mt_2d, 256, GSMEM, s2>>>(p_memh, p_wh + OW_CA_IN + (size_t)DMODEL*DMODEL,
                                          ca_in_b + DMODEL, nullptr, p_kvh, MTOK, 2048, DMODEL, 4);
    cudaEventRecord(evJoin, s2);

    // ---- main stream: self-attention block ----
    ln_kernel<<<NT, 256>>>(tgt, ln1_g, ln1_b, p_hh, p_ropedh);   // fused LN+RoPE
    hgemm<<<gemm_nt_2d, 256, GSMEM>>>(p_ropedh, p_wh + OW_SA_IN, sa_in_b, nullptr, p_qkh, NT, 2048, DMODEL, 4);
    hgemm<<<gemm_nt_d, 256, GSMEM>>>(p_hh, p_wh + OW_SA_IN + (size_t)2*DMODEL*DMODEL, sa_in_b + 2*DMODEL, nullptr, p_vh, NT, DMODEL, DMODEL, 4);
    attn_h<<<dim3(qtiles, NH, BB), 256>>>(p_qkh, p_qkh + 1024, p_vh, p_attnh, SQ, SQ, 1, 2048, 2048, 1024);
    hgemm<<<gemm_nt_d, 256, GSMEM>>>(p_attnh, p_wh + OW_SA_OUT, sa_out_b, tgt, p_x, NT, DMODEL, DMODEL, 2);

    // ---- cross-attention block ----
    ln_kernel<<<NT, 256>>>(p_x, ln2_g, ln2_b, p_hh, nullptr);
    hgemm<<<gemm_nt_d, 256, GSMEM>>>(p_hh, p_wh + OW_CA_IN, ca_in_b, nullptr, p_qh, NT, DMODEL, DMODEL, 4);
    cudaStreamWaitEvent(0, evJoin, 0);   // join: kv GEMM must be done
    attn_h<<<dim3(qtiles, NH, BB), 256>>>(p_qh, p_kvh, p_kvh + 1024, p_attnh, SQ, SMEMLEN, 0, 1024, 2048, 2048);
    hgemm<<<gemm_nt_d, 256, GSMEM>>>(p_attnh, p_wh + OW_CA_OUT, ca_out_b, p_x, p_x, NT, DMODEL, DMODEL, 2);

    // ---- feed-forward block ----
    ln_kernel<<<NT, 256>>>(p_x, ln3_g, ln3_b, p_hh, nullptr);
    hgemm<<<gemm_ff1, 256, GSMEM>>>(p_hh,   p_wh + OW_FF1, ff1_b, nullptr, p_ffhh, NT, DFF, DMODEL, 1 | 4);
    hgemm<<<gemm_nt_d, 256, GSMEM>>>(p_ffhh, p_wh + OW_FF2, ff2_b, p_x, out, NT, DMODEL, DFF, 2);
}

// round 16
// speedup vs baseline: 1.2545x; 1.0183x over previous
#include <cuda_runtime.h>
#include <cuda_fp16.h>
#include <math.h>

#define BB 32
#define SQ 200
#define SMEMLEN 1024
#define DMODEL 1024
#define NH 16
#define HD 64
#define DFF 4096
#define NT (BB*SQ)        // 6400 target tokens
#define MTOK (BB*SMEMLEN) // 32768 memory tokens
#define EPS 1e-5f

// ---------------- scratch ----------------
__device__ float  g_x[NT*DMODEL];
__device__ __half g_qkh[NT*2048];       // SA q|k packed (row stride 2048)
__device__ __half g_vh[NT*DMODEL];      // SA v
__device__ __half g_qh[NT*DMODEL];      // CA q
__device__ __half g_kvh[MTOK*2048];     // CA k|v packed (row stride 2048)
__device__ __half g_hh[NT*DMODEL];
__device__ __half g_ropedh[NT*DMODEL];
__device__ __half g_attnh[NT*DMODEL];
__device__ __half g_ffhh[NT*DFF];
__device__ __half g_memh[MTOK*DMODEL];
__device__ __half g_wh[16*1024*1024];   // fp16 weights (packed)

#define OW_SA_IN   0
#define OW_SA_OUT  3145728
#define OW_CA_IN   4194304
#define OW_CA_OUT  7340032
#define OW_FF1     8388608
#define OW_FF2     12582912

// ---------------- single fp32->fp16 convert ----------------
__global__ void to_half_kernel(const float4* __restrict__ in,
                               uint2* __restrict__ out, int n4) {
    int idx = blockIdx.x * blockDim.x + threadIdx.x;
    int T = gridDim.x * blockDim.x;
    for (int base = idx; base < n4; base += 4 * T) {
        #pragma unroll
        for (int u = 0; u < 4; u++) {
            int k = base + u * T;
            if (k < n4) {
                float4 v = in[k];
                __half2 h0 = __floats2half2_rn(v.x, v.y);
                __half2 h1 = __floats2half2_rn(v.z, v.w);
                uint2 o; o.x = *(unsigned*)&h0; o.y = *(unsigned*)&h1;
                out[k] = o;
            }
        }
    }
}

// ---------------- merged 6-segment weight convert ----------------
#define SEG0 786432
#define SEG1 (SEG0 + 262144)
#define SEG2 (SEG1 + 786432)
#define SEG3 (SEG2 + 262144)
#define SEG4 (SEG3 + 1048576)
#define SEGT (SEG4 + 1048576)
__global__ void to_half_multi(const float4* __restrict__ s0, const float4* __restrict__ s1,
                              const float4* __restrict__ s2, const float4* __restrict__ s3,
                              const float4* __restrict__ s4, const float4* __restrict__ s5,
                              uint2* __restrict__ dst) {
    int idx = blockIdx.x * blockDim.x + threadIdx.x;
    int T = gridDim.x * blockDim.x;
    for (int base = idx; base < SEGT; base += 4 * T) {
        #pragma unroll
        for (int u = 0; u < 4; u++) {
            int k = base + u * T;
            if (k < SEGT) {
                float4 v;
                if      (k < SEG0) v = s0[k];
                else if (k < SEG1) v = s1[k - SEG0];
                else if (k < SEG2) v = s2[k - SEG1];
                else if (k < SEG3) v = s3[k - SEG2];
                else if (k < SEG4) v = s4[k - SEG3];
                else               v = s5[k - SEG4];
                __half2 h0 = __floats2half2_rn(v.x, v.y);
                __half2 h1 = __floats2half2_rn(v.z, v.w);
                uint2 o; o.x = *(unsigned*)&h0; o.y = *(unsigned*)&h1;
                dst[k] = o;
            }
        }
    }
}

// ---------------- LayerNorm (fp32 in, fp16 out; optional fused RoPE out) -------
__global__ __launch_bounds__(256) void ln_kernel(const float* __restrict__ x,
                                                 const float* __restrict__ g,
                                                 const float* __restrict__ b,
                                                 __half* __restrict__ out,
                                                 __half* __restrict__ out_roped) {
    __shared__ float rs[8], rss[8];
    int t = blockIdx.x;
    int tid = threadIdx.x;
    const float4* xr = (const float4*)(x + (size_t)t * DMODEL);
    float4 v = xr[tid];
    float s  = v.x + v.y + v.z + v.w;
    float ss = v.x*v.x + v.y*v.y + v.z*v.z + v.w*v.w;
    #pragma unroll
    for (int o = 16; o; o >>= 1) {
        s  += __shfl_xor_sync(0xffffffffu, s, o);
        ss += __shfl_xor_sync(0xffffffffu, ss, o);
    }
    int lane = tid & 31, wid = tid >> 5;
    if (lane == 0) { rs[wid] = s; rss[wid] = ss; }
    __syncthreads();
    float ts = 0.f, tss = 0.f;
    #pragma unroll
    for (int w = 0; w < 8; w++) { ts += rs[w]; tss += rss[w]; }
    float mu  = ts * (1.0f / DMODEL);
    float var = tss * (1.0f / DMODEL) - mu * mu;
    float r   = rsqrtf(var + EPS);
    float4 gv = ((const float4*)g)[tid];
    float4 bv = ((const float4*)b)[tid];
    float ox = (v.x - mu) * r * gv.x + bv.x;
    float oy = (v.y - mu) * r * gv.y + bv.y;
    float oz = (v.z - mu) * r * gv.z + bv.z;
    float ow = (v.w - mu) * r * gv.w + bv.w;
    {
        __half2 h0 = __floats2half2_rn(ox, oy);
        __half2 h1 = __floats2half2_rn(oz, ow);
        uint2 o;
        o.x = *(unsigned*)&h0;
        o.y = *(unsigned*)&h1;
        ((uint2*)(out + (size_t)t * DMODEL))[tid] = o;
    }
    if (out_roped) {
        int e0 = tid * 4;
        int i0 = (e0 & 63) >> 1;
        int spos = t % SQ;
        float f0 = __expf(-9.210340371976184f * (2.0f * i0) * (1.0f / 64.0f));
        float f1 = __expf(-9.210340371976184f * (2.0f * (i0 + 1)) * (1.0f / 64.0f));
        float sn0, cs0, sn1, cs1;
        sincosf((float)spos * f0, &sn0, &cs0);
        sincosf((float)spos * f1, &sn1, &cs1);
        float r0x = ox * cs0 - oy * sn0;
        float r0y = oy * cs0 + ox * sn0;
        float r1x = oz * cs1 - ow * sn1;
        float r1y = ow * cs1 + oz * sn1;
        __half2 h0 = __floats2half2_rn(r0x, r0y);
        __half2 h1 = __floats2half2_rn(r1x, r1y);
        uint2 o;
        o.x = *(unsigned*)&h0;
        o.y = *(unsigned*)&h1;
        ((uint2*)(out_roped + (size_t)t * DMODEL))[tid] = o;
    }
}

// ---------------- common mma helpers ----------------
__device__ __forceinline__ void cpa16(unsigned dst, const void* src) {
    asm volatile("cp.async.cg.shared.global [%0], [%1], 16;\n" :: "r"(dst), "l"(src));
}
__device__ __forceinline__ void ldsm4(unsigned& r0, unsigned& r1, unsigned& r2, unsigned& r3,
                                      unsigned a) {
    asm volatile("ldmatrix.sync.aligned.m8n8.x4.shared.b16 {%0,%1,%2,%3}, [%4];"
                 : "=r"(r0), "=r"(r1), "=r"(r2), "=r"(r3) : "r"(a));
}
__device__ __forceinline__ void ldsm4t(unsigned& r0, unsigned& r1, unsigned& r2, unsigned& r3,
                                       unsigned a) {
    asm volatile("ldmatrix.sync.aligned.m8n8.x4.trans.shared.b16 {%0,%1,%2,%3}, [%4];"
                 : "=r"(r0), "=r"(r1), "=r"(r2), "=r"(r3) : "r"(a));
}
__device__ __forceinline__ void mma16816(float* c, unsigned a0, unsigned a1, unsigned a2,
                                         unsigned a3, unsigned b0, unsigned b1) {
    asm volatile(
        "mma.sync.aligned.m16n8k16.row.col.f32.f16.f16.f32 "
        "{%0,%1,%2,%3}, {%4,%5,%6,%7}, {%8,%9}, {%0,%1,%2,%3};"
        : "+f"(c[0]), "+f"(c[1]), "+f"(c[2]), "+f"(c[3])
        : "r"(a0), "r"(a1), "r"(a2), "r"(a3), "r"(b0), "r"(b1));
}

// ---------------- fp16 tensor-core GEMM (128x128, 3-stage, dual-A/dual-C) ------
// C[:, 0:split)      = A  @ W[0:split)^T      -> Cout  (row stride = split)
// C[:, split:N)      = A2 @ W[split:N)^T      -> Cout2 (row stride = N - split)
// bias is contiguous over all N columns. flags: 1 relu, 2 fp32 res, 4 fp16 out.
#define BKH 64
#define RSH 72
#define NSTG 3
#define STGH (2 * 128 * RSH)
#define GSMEM (NSTG * STGH * 2)          // 110592 bytes

__global__ __launch_bounds__(256, 2) void hgemm(const __half* __restrict__ A,
                                                const __half* __restrict__ A2,
                                                const __half* __restrict__ W,
                                                const float* __restrict__ bias,
                                                const float* __restrict__ res,
                                                void* __restrict__ Cout,
                                                void* __restrict__ Cout2,
                                                int M, int N, int split,
                                                int K, int flags) {
    extern __shared__ __half smh[];
    int tid = threadIdx.x;
    int wid = tid >> 5, lane = tid & 31;
    int gid = lane >> 2, tig = lane & 3;
    int row0 = blockIdx.y * 128;
    int col0 = blockIdx.x * 128;
    int wm = (wid & 3) * 32;
    int wn = (wid >> 2) * 64;

    bool first = (col0 < split);
    const __half* Ause = first ? A : A2;
    void* Co      = first ? Cout : Cout2;
    int strideo   = first ? split : (N - split);
    int cbase     = first ? 0 : split;

    unsigned sbase = (unsigned)__cvta_generic_to_shared(smh);
    unsigned stgA[NSTG], stgW[NSTG];
    #pragma unroll
    for (int s = 0; s < NSTG; s++) {
        stgA[s] = sbase + s * STGH * 2;
        stgW[s] = stgA[s] + 128 * RSH * 2;
    }

    int lr = tid >> 1;
    int lc = (tid & 1) * 32;
    const __half* Ab = Ause + (size_t)(row0 + lr) * K + lc;
    const __half* Wb = W + (size_t)(col0 + lr) * K + lc;

    float c[2][8][4];
    #pragma unroll
    for (int mi = 0; mi < 2; mi++)
        #pragma unroll
        for (int ni = 0; ni < 8; ni++)
            #pragma unroll
            for (int q = 0; q < 4; q++) c[mi][ni][q] = 0.f;

    int nk = K / BKH;

    #pragma unroll
    for (int ps = 0; ps < 2; ps++) {
        int k0 = ps * BKH;
        #pragma unroll
        for (int cch = 0; cch < 4; cch++) {
            unsigned soff = (lr * RSH + lc + cch * 8) * 2;
            cpa16(stgA[ps] + soff, Ab + k0 + cch * 8);
            cpa16(stgW[ps] + soff, Wb + k0 + cch * 8);
        }
        asm volatile("cp.async.commit_group;\n");
    }

    int a_row = lane & 15;
    int a_col = (lane >> 4) * 8;
    int b_row = (lane & 7) + ((lane & 16) >> 1);
    int b_col = lane & 8;

    unsigned af[2][2][4], bf[2][4][4];

    for (int kt = 0; kt < nk; kt++) {
        if (kt < nk - 1) asm volatile("cp.async.wait_group 1;\n");
        else             asm volatile("cp.async.wait_group 0;\n");
        __syncthreads();

        if (kt + 2 < nk) {
            int st = (kt + 2) % NSTG;
            int k0 = (kt + 2) * BKH;
            #pragma unroll
            for (int cch = 0; cch < 4; cch++) {
                unsigned soff = (lr * RSH + lc + cch * 8) * 2;
                cpa16(stgA[st] + soff, Ab + k0 + cch * 8);
                cpa16(stgW[st] + soff, Wb + k0 + cch * 8);
            }
            asm volatile("cp.async.commit_group;\n");
        }

        int st = kt % NSTG;
        unsigned sAu = stgA[st];
        unsigned sWu = stgW[st];

        auto load_frags = [&](int buf, int ks) {
            int kb = ks * 16;
            #pragma unroll
            for (int mi = 0; mi < 2; mi++)
                ldsm4(af[buf][mi][0], af[buf][mi][1], af[buf][mi][2], af[buf][mi][3],
                      sAu + ((wm + mi * 16 + a_row) * RSH + kb + a_col) * 2);
            #pragma unroll
            for (int p = 0; p < 4; p++)
                ldsm4(bf[buf][p][0], bf[buf][p][1], bf[buf][p][2], bf[buf][p][3],
                      sWu + ((wn + p * 16 + b_row) * RSH + kb + b_col) * 2);
        };

        load_frags(0, 0);
        #pragma unroll
        for (int ks = 0; ks < 4; ks++) {
            int cur = ks & 1;
            if (ks < 3) load_frags(cur ^ 1, ks + 1);
            #pragma unroll
            for (int mi = 0; mi < 2; mi++)
                #pragma unroll
                for (int p = 0; p < 4; p++) {
                    mma16816(c[mi][2*p],   af[cur][mi][0], af[cur][mi][1], af[cur][mi][2],
                             af[cur][mi][3], bf[cur][p][0], bf[cur][p][1]);
                    mma16816(c[mi][2*p+1], af[cur][mi][0], af[cur][mi][1], af[cur][mi][2],
                             af[cur][mi][3], bf[cur][p][2], bf[cur][p][3]);
                }
        }
    }

    bool use_relu = (flags & 1) != 0;
    bool use_res  = (flags & 2) != 0;
    bool out_h    = (flags & 4) != 0;
    float* Cf = (float*)Co;
    __half* Ch = (__half*)Co;
    #pragma unroll
    for (int mi = 0; mi < 2; mi++) {
        #pragma unroll
        for (int ni = 0; ni < 8; ni++) {
            int colg = col0 + wn + ni * 8 + tig * 2;
            int r0 = row0 + wm + mi * 16 + gid;
            int r1 = r0 + 8;
            float b0 = bias[colg], b1 = bias[colg + 1];
            int cl = colg - cbase;
            float2 o0, o1;
            o0.x = c[mi][ni][0] + b0; o0.y = c[mi][ni][1] + b1;
            o1.x = c[mi][ni][2] + b0; o1.y = c[mi][ni][3] + b1;
            size_t i0 = (size_t)r0 * strideo + cl;
            size_t i1 = (size_t)r1 * strideo + cl;
            if (use_res) {
                float2 rv0 = *(const float2*)(res + i0);
                float2 rv1 = *(const float2*)(res + i1);
                o0.x += rv0.x; o0.y += rv0.y;
                o1.x += rv1.x; o1.y += rv1.y;
            }
            if (use_relu) {
                o0.x = fmaxf(o0.x, 0.f); o0.y = fmaxf(o0.y, 0.f);
                o1.x = fmaxf(o1.x, 0.f); o1.y = fmaxf(o1.y, 0.f);
            }
            if (out_h) {
                __half2 h0 = __floats2half2_rn(o0.x, o0.y);
                __half2 h1 = __floats2half2_rn(o1.x, o1.y);
                *(unsigned*)(Ch + i0) = *(unsigned*)&h0;
                *(unsigned*)(Ch + i1) = *(unsigned*)&h1;
            } else {
                *(float2*)(Cf + i0) = o0;
                *(float2*)(Cf + i1) = o1;
            }
        }
    }
}

// ---------------- fp16 tensor-core flash attention (AQ=128, 8 warps) ----------
#define AQ 128
#define AK 64
#define AH 72   // halves per smem row

__global__ __launch_bounds__(256) void attn_h(const __half* __restrict__ Q,
                                              const __half* __restrict__ Km,
                                              const __half* __restrict__ Vm,
                                              __half* __restrict__ O,
                                              int Sq, int Sk, int causal,
                                              int qstr, int kstr, int vstr) {
    __shared__ __half Qs[AQ*AH], Ks[AK*AH], Vs[AK*AH];

    int qt = blockIdx.x, h = blockIdx.y, b = blockIdx.z;
    int tid = threadIdx.x;
    int wid = tid >> 5, lane = tid & 31;

    unsigned sQ = (unsigned)__cvta_generic_to_shared(Qs);
    unsigned sK = (unsigned)__cvta_generic_to_shared(Ks);
    unsigned sV = (unsigned)__cvta_generic_to_shared(Vs);

    {
        int r = tid >> 1;
        int cb = (tid & 1) * 32;
        int qgl = qt * AQ + r;
        const __half* src = Q + ((size_t)(b * Sq + qgl)) * qstr + h * HD + cb;
        uint4 z = {0u, 0u, 0u, 0u};
        #pragma unroll
        for (int i = 0; i < 4; i++) {
            uint4 v = (qgl < Sq) ? *(const uint4*)(src + i * 8) : z;
            *(uint4*)&Qs[r * AH + cb + i * 8] = v;
        }
    }
    __syncthreads();

    int a_row = lane & 15;
    int a_col = (lane >> 4) * 8;
    unsigned aq[4][4];
    #pragma unroll
    for (int ks = 0; ks < 4; ks++)
        ldsm4(aq[ks][0], aq[ks][1], aq[ks][2], aq[ks][3],
              sQ + ((wid * 16 + a_row) * AH + ks * 16 + a_col) * 2);

    int b_row = (lane & 7) + ((lane & 16) >> 1);
    int b_col = lane & 8;

    int r0 = lane >> 2, tig = lane & 3;
    int qgl0 = qt * AQ + wid * 16 + r0;
    int qgl1 = qgl0 + 8;
    float m0 = -1e30f, m1 = -1e30f, l0 = 0.f, l1 = 0.f;
    float o[8][4];
    #pragma unroll
    for (int j = 0; j < 8; j++)
        #pragma unroll
        for (int q = 0; q < 4; q++) o[j][q] = 0.f;

    int q_hi = qt * AQ + AQ - 1;
    int keff = causal ? min(q_hi + 1, Sk) : Sk;
    int ntiles = (keff + AK - 1) / AK;

    int kr = tid >> 3;
    int kc = (tid & 7) * 8;
    uint4 pk[2], pv[2];
    {
        uint4 z = {0u, 0u, 0u, 0u};
        #pragma unroll
        for (int j2 = 0; j2 < 2; j2++) {
            int kg = kr + 32 * j2;
            bool ok = kg < Sk;
            pk[j2] = ok ? *(const uint4*)(Km + ((size_t)(b * Sk + kg)) * kstr + h * HD + kc) : z;
            pv[j2] = ok ? *(const uint4*)(Vm + ((size_t)(b * Sk + kg)) * vstr + h * HD + kc) : z;
        }
    }

    for (int kt = 0; kt < ntiles; kt++) {
        #pragma unroll
        for (int j2 = 0; j2 < 2; j2++) {
            *(uint4*)&Ks[(kr + 32 * j2) * AH + kc] = pk[j2];
            *(uint4*)&Vs[(kr + 32 * j2) * AH + kc] = pv[j2];
        }
        __syncthreads();

        if (kt + 1 < ntiles) {
            uint4 z = {0u, 0u, 0u, 0u};
            #pragma unroll
            for (int j2 = 0; j2 < 2; j2++) {
                int kg = (kt + 1) * AK + kr + 32 * j2;
                bool ok = kg < Sk;
                pk[j2] = ok ? *(const uint4*)(Km + ((size_t)(b * Sk + kg)) * kstr + h * HD + kc) : z;
                pv[j2] = ok ? *(const uint4*)(Vm + ((size_t)(b * Sk + kg)) * vstr + h * HD + kc) : z;
            }
        }

        float s[8][4];
        #pragma unroll
        for (int j = 0; j < 8; j++)
            #pragma unroll
            for (int q = 0; q < 4; q++) s[j][q] = 0.f;

        #pragma unroll
        for (int ks = 0; ks < 4; ks++) {
            #pragma unroll
            for (int p = 0; p < 4; p++) {
                unsigned bf0, bf1, bf2, bf3;
                ldsm4(bf0, bf1, bf2, bf3,
                      sK + ((p * 16 + b_row) * AH + ks * 16 + b_col) * 2);
                mma16816(s[2*p],   aq[ks][0], aq[ks][1], aq[ks][2], aq[ks][3], bf0, bf1);
                mma16816(s[2*p+1], aq[ks][0], aq[ks][1], aq[ks][2], aq[ks][3], bf2, bf3);
            }
        }

        int kvalid0 = causal ? min(qgl0 + 1, Sk) : Sk;
        int kvalid1 = causal ? min(qgl1 + 1, Sk) : Sk;
        int kgb = kt * AK + tig * 2;
        float tm0 = -1e30f, tm1 = -1e30f;
        #pragma unroll
        for (int j = 0; j < 8; j++) {
            int kg = kgb + j * 8;
            s[j][0] = (kg     < kvalid0) ? s[j][0] * 0.125f : -1e30f;
            s[j][1] = (kg + 1 < kvalid0) ? s[j][1] * 0.125f : -1e30f;
            s[j][2] = (kg     < kvalid1) ? s[j][2] * 0.125f : -1e30f;
            s[j][3] = (kg + 1 < kvalid1) ? s[j][3] * 0.125f : -1e30f;
            tm0 = fmaxf(tm0, fmaxf(s[j][0], s[j][1]));
            tm1 = fmaxf(tm1, fmaxf(s[j][2], s[j][3]));
        }
        tm0 = fmaxf(tm0, __shfl_xor_sync(0xffffffffu, tm0, 1));
        tm0 = fmaxf(tm0, __shfl_xor_sync(0xffffffffu, tm0, 2));
        tm1 = fmaxf(tm1, __shfl_xor_sync(0xffffffffu, tm1, 1));
        tm1 = fmaxf(tm1, __shfl_xor_sync(0xffffffffu, tm1, 2));

        float mn0 = fmaxf(m0, tm0), mn1 = fmaxf(m1, tm1);
        float sc0 = __expf(m0 - mn0), sc1 = __expf(m1 - mn1);
        float ps0 = 0.f, ps1 = 0.f;
        #pragma unroll
        for (int j = 0; j < 8; j++) {
            s[j][0] = __expf(s[j][0] - mn0);
            s[j][1] = __expf(s[j][1] - mn0);
            s[j][2] = __expf(s[j][2] - mn1);
            s[j][3] = __expf(s[j][3] - mn1);
            ps0 += s[j][0] + s[j][1];
            ps1 += s[j][2] + s[j][3];
        }
        ps0 += __shfl_xor_sync(0xffffffffu, ps0, 1);
        ps0 += __shfl_xor_sync(0xffffffffu, ps0, 2);
        ps1 += __shfl_xor_sync(0xffffffffu, ps1, 1);
        ps1 += __shfl_xor_sync(0xffffffffu, ps1, 2);
        l0 = l0 * sc0 + ps0;  m0 = mn0;
        l1 = l1 * sc1 + ps1;  m1 = mn1;
        #pragma unroll
        for (int j = 0; j < 8; j++) {
            o[j][0] *= sc0; o[j][1] *= sc0;
            o[j][2] *= sc1; o[j][3] *= sc1;
        }

        unsigned pa[4][4];
        #pragma unroll
        for (int t = 0; t < 4; t++) {
            __half2 h0 = __floats2half2_rn(s[2*t][0],   s[2*t][1]);
            __half2 h1 = __floats2half2_rn(s[2*t][2],   s[2*t][3]);
            __half2 h2 = __floats2half2_rn(s[2*t+1][0], s[2*t+1][1]);
            __half2 h3 = __floats2half2_rn(s[2*t+1][2], s[2*t+1][3]);
            pa[t][0] = *(unsigned*)&h0;
            pa[t][1] = *(unsigned*)&h1;
            pa[t][2] = *(unsigned*)&h2;
            pa[t][3] = *(unsigned*)&h3;
        }

        #pragma unroll
        for (int t = 0; t < 4; t++) {
            #pragma unroll
            for (int p = 0; p < 4; p++) {
                unsigned bv0, bv1, bv2, bv3;
                ldsm4t(bv0, bv1, bv2, bv3,
                       sV + ((t * 16 + (lane & 15)) * AH + p * 16 + (lane >> 4) * 8) * 2);
                mma16816(o[2*p],   pa[t][0], pa[t][1], pa[t][2], pa[t][3], bv0, bv1);
                mma16816(o[2*p+1], pa[t][0], pa[t][1], pa[t][2], pa[t][3], bv2, bv3);
            }
        }
        __syncthreads();
    }

    float inv0 = 1.0f / l0, inv1 = 1.0f / l1;
    #pragma unroll
    for (int j = 0; j < 8; j++) {
        int d = j * 8 + tig * 2;
        if (qgl0 < Sq) {
            __half2 h0 = __floats2half2_rn(o[j][0] * inv0, o[j][1] * inv0);
            *(unsigned*)(O + ((size_t)(b * Sq + qgl0)) * DMODEL + h * HD + d) = *(unsigned*)&h0;
        }
        if (qgl1 < Sq) {
            __half2 h1 = __floats2half2_rn(o[j][2] * inv1, o[j][3] * inv1);
            *(unsigned*)(O + ((size_t)(b * Sq + qgl1)) * DMODEL + h * HD + d) = *(unsigned*)&h1;
        }
    }
}

// ---------------- host orchestration ----------------
extern "C" void kernel_launch(void* const* d_in, const int* in_sizes, int n_in,
                              void* d_out, int out_size) {
    const float* tgt      = (const float*)d_in[0];
    const float* memory   = (const float*)d_in[1];
    const float* sa_in_w  = (const float*)d_in[2];
    const float* sa_in_b  = (const float*)d_in[3];
    const float* sa_out_w = (const float*)d_in[4];
    const float* sa_out_b = (const float*)d_in[5];
    const float* ca_in_w  = (const float*)d_in[6];
    const float* ca_in_b  = (const float*)d_in[7];
    const float* ca_out_w = (const float*)d_in[8];
    const float* ca_out_b = (const float*)d_in[9];
    const float* ff1_w    = (const float*)d_in[10];
    const float* ff1_b    = (const float*)d_in[11];
    const float* ff2_w    = (const float*)d_in[12];
    const float* ff2_b    = (const float*)d_in[13];
    const float* ln1_g    = (const float*)d_in[14];
    const float* ln1_b    = (const float*)d_in[15];
    const float* ln2_g    = (const float*)d_in[16];
    const float* ln2_b    = (const float*)d_in[17];
    const float* ln3_g    = (const float*)d_in[18];
    const float* ln3_b    = (const float*)d_in[19];
    float* out = (float*)d_out;

    float *p_x;
    __half *p_qkh, *p_vh, *p_qh, *p_kvh, *p_hh, *p_ropedh, *p_attnh, *p_ffhh, *p_memh, *p_wh;
    cudaGetSymbolAddress((void**)&p_x,      g_x);
    cudaGetSymbolAddress((void**)&p_qkh,    g_qkh);
    cudaGetSymbolAddress((void**)&p_vh,     g_vh);
    cudaGetSymbolAddress((void**)&p_qh,     g_qh);
    cudaGetSymbolAddress((void**)&p_kvh,    g_kvh);
    cudaGetSymbolAddress((void**)&p_hh,     g_hh);
    cudaGetSymbolAddress((void**)&p_ropedh, g_ropedh);
    cudaGetSymbolAddress((void**)&p_attnh,  g_attnh);
    cudaGetSymbolAddress((void**)&p_ffhh,   g_ffhh);
    cudaGetSymbolAddress((void**)&p_memh,   g_memh);
    cudaGetSymbolAddress((void**)&p_wh,     g_wh);

    static int init_done = 0;
    static cudaStream_t s2;
    static cudaEvent_t evFork, evJoin;
    if (!init_done) {
        cudaFuncSetAttribute(hgemm, cudaFuncAttributeMaxDynamicSharedMemorySize, GSMEM);
        cudaStreamCreateWithFlags(&s2, cudaStreamNonBlocking);
        cudaEventCreateWithFlags(&evFork, cudaEventDisableTiming);
        cudaEventCreateWithFlags(&evJoin, cudaEventDisableTiming);
        init_done = 1;
    }

    dim3 gemm_nt_d(DMODEL / 128, NT / 128);         // (8, 50)
    dim3 gemm_sa_qkv(3072 / 128, NT / 128);         // (24, 50) merged q|k|v
    dim3 gemm_mt_2d(2048 / 128, MTOK / 128);        // (16, 256) merged k|v
    dim3 gemm_ff1(DFF / 128, NT / 128);             // (32, 50)
    int qtiles = (SQ + AQ - 1) / AQ;                // 2

    // ---- all six weight converts in ONE launch ----
    to_half_multi<<<1024, 256>>>((const float4*)sa_in_w, (const float4*)sa_out_w,
                                 (const float4*)ca_in_w, (const float4*)ca_out_w,
                                 (const float4*)ff1_w,   (const float4*)ff2_w,
                                 (uint2*)p_wh);

    // ---- fork: stream2 does memory convert + big CA k|v GEMM concurrently ----
    cudaEventRecord(evFork, 0);
    cudaStreamWaitEvent(s2, evFork, 0);
    {
        int n4 = (MTOK * DMODEL) / 4;
        to_half_kernel<<<(n4 + 1023) / 1024, 256, 0, s2>>>((const float4*)memory, (uint2*)p_memh, n4);
    }
    hgemm<<<gemm_mt_2d, 256, GSMEM, s2>>>(p_memh, p_memh,
                                          p_wh + OW_CA_IN + (size_t)DMODEL*DMODEL,
                                          ca_in_b + DMODEL, nullptr,
                                          p_kvh, p_kvh, MTOK, 2048, 2048, DMODEL, 4);
    cudaEventRecord(evJoin, s2);

    // ---- main stream: self-attention block ----
    ln_kernel<<<NT, 256>>>(tgt, ln1_g, ln1_b, p_hh, p_ropedh);   // fused LN+RoPE
    // merged q|k (A=roped) + v (A=hh) projection: one 1200-CTA launch
    hgemm<<<gemm_sa_qkv, 256, GSMEM>>>(p_ropedh, p_hh, p_wh + OW_SA_IN, sa_in_b, nullptr,
                                       p_qkh, p_vh, NT, 3072, 2048, DMODEL, 4);
    attn_h<<<dim3(qtiles, NH, BB), 256>>>(p_qkh, p_qkh + 1024, p_vh, p_attnh, SQ, SQ, 1, 2048, 2048, 1024);
    hgemm<<<gemm_nt_d, 256, GSMEM>>>(p_attnh, p_attnh, p_wh + OW_SA_OUT, sa_out_b, tgt,
                                     p_x, p_x, NT, DMODEL, DMODEL, DMODEL, 2);

    // ---- cross-attention block ----
    ln_kernel<<<NT, 256>>>(p_x, ln2_g, ln2_b, p_hh, nullptr);
    hgemm<<<gemm_nt_d, 256, GSMEM>>>(p_hh, p_hh, p_wh + OW_CA_IN, ca_in_b, nullptr,
                                     p_qh, p_qh, NT, DMODEL, DMODEL, DMODEL, 4);
    cudaStreamWaitEvent(0, evJoin, 0);   // join: kv GEMM must be done
    attn_h<<<dim3(qtiles, NH, BB), 256>>>(p_qh, p_kvh, p_kvh + 1024, p_attnh, SQ, SMEMLEN, 0, 1024, 2048, 2048);
    hgemm<<<gemm_nt_d, 256, GSMEM>>>(p_attnh, p_attnh, p_wh + OW_CA_OUT, ca_out_b, p_x,
                                     p_x, p_x, NT, DMODEL, DMODEL, DMODEL, 2);

    // ---- feed-forward block ----
    ln_kernel<<<NT, 256>>>(p_x, ln3_g, ln3_b, p_hh, nullptr);
    hgemm<<<gemm_ff1, 256, GSMEM>>>(p_hh, p_hh, p_wh + OW_FF1, ff1_b, nullptr,
                                    p_ffhh, p_ffhh, NT, DFF, DFF, DMODEL, 1 | 4);
    hgemm<<<gemm_nt_d, 256, GSMEM>>>(p_ffhh, p_ffhh, p_wh + OW_FF2, ff2_b, p_x,
                                     out, out, NT, DMODEL, DMODEL, DFF, 2);
}